// round 10
// baseline (speedup 1.0000x reference)
#include <cuda_runtime.h>
#include <cstdint>

#define Bn   16
#define Tn   512
#define INn  128
#define Hn   256
#define Dn   8
#define EPSf 1e-5f

#define SCAN_CTAS 32
#define GRID_SCAN 256          // 32 scan CTAs + 224 zero-fill CTAs

// ---------------- scratch (static device arrays; no allocation) ----------------
__device__ float g_xproj[Bn * Tn * Hn];   // 8 MB
__device__ float g_enc  [Bn * Tn * Hn];   // 8 MB
__device__ float g_bd   [Bn * Tn * 2 * Dn]; // 512 KB

// ---------------- helpers ----------------
__device__ __forceinline__ uint32_t smem_u32(const void* p) {
    uint32_t a;
    asm("{ .reg .u64 t; cvta.to.shared.u64 t, %1; cvt.u32.u64 %0, t; }"
        : "=r"(a) : "l"(p));
    return a;
}

__device__ __forceinline__ uint32_t cluster_rank() {
    uint32_t r;
    asm("mov.u32 %0, %%cluster_ctarank;" : "=r"(r));
    return r;
}

__device__ __forceinline__ uint32_t mapa_u32(uint32_t local_addr, uint32_t rank) {
    uint32_t r;
    asm("mapa.shared::cluster.u32 %0, %1, %2;" : "=r"(r) : "r"(local_addr), "r"(rank));
    return r;
}

__device__ __forceinline__ unsigned long long pack2(float x, float y) {
    unsigned long long r;
    asm("mov.b64 %0, {%1, %2};" : "=l"(r) : "f"(x), "f"(y));
    return r;
}
__device__ __forceinline__ void unpack2(unsigned long long v, float& x, float& y) {
    asm("mov.b64 {%0, %1}, %2;" : "=f"(x), "=f"(y) : "l"(v));
}
// packed fp32x2 FMA (Blackwell FFMA2): 2 fp32 MACs per instruction
__device__ __forceinline__ void ffma2(unsigned long long& d,
                                      unsigned long long a,
                                      unsigned long long b) {
    asm("fma.rn.f32x2 %0, %1, %2, %3;" : "=l"(d) : "l"(a), "l"(b), "l"(d));
}

__device__ __forceinline__ float tanh_approx(float x) {
    float r;
    asm("tanh.approx.f32 %0, %1;" : "=f"(r) : "f"(x));
    return r;
}

__device__ __forceinline__ void mbar_init(uint32_t addr, uint32_t count) {
    asm volatile("mbarrier.init.shared.b64 [%0], %1;" :: "r"(addr), "r"(count) : "memory");
}

__device__ __forceinline__ void mbar_arrive_expect_tx(uint32_t addr, uint32_t bytes) {
    asm volatile("mbarrier.arrive.expect_tx.shared.b64 _, [%0], %1;"
                 :: "r"(addr), "r"(bytes) : "memory");
}

__device__ __forceinline__ void mbar_wait(uint32_t addr, int phase) {
    asm volatile(
        "{\n\t"
        ".reg .pred P1;\n\t"
        "LAB_%=:\n\t"
        "mbarrier.try_wait.parity.acquire.cta.shared::cta.b64 P1, [%0], %1, 0x989680;\n\t"
        "@P1 bra DONE_%=;\n\t"
        "bra LAB_%=;\n\t"
        "DONE_%=:\n\t"
        "}"
        :: "r"(addr), "r"(phase) : "memory");
}

// async remote smem store (b32) with tx-completion on the remote mbarrier
__device__ __forceinline__ void st_async_f32(uint32_t raddr, float v, uint32_t rmbar) {
    asm volatile(
        "st.async.shared::cluster.mbarrier::complete_tx::bytes.b32 [%0], %1, [%2];"
        :: "r"(raddr), "r"(__float_as_uint(v)), "r"(rmbar) : "memory");
}

// ---------------- kernel 1: x_proj = y @ W_ih^T + b_ih ----------------
__global__ void k_xproj(const float* __restrict__ y,
                        const float* __restrict__ W_ih,
                        const float* __restrict__ b_ih) {
    const int h  = threadIdx.x;       // 0..255
    const int b  = blockIdx.y;
    const int t0 = blockIdx.x * 4;

    const float4* Wr = reinterpret_cast<const float4*>(W_ih + h * INn);
    const float4* Y  = reinterpret_cast<const float4*>(y + ((size_t)b * Tn + t0) * INn);

    float a0 = 0.f, a1 = 0.f, a2 = 0.f, a3 = 0.f;
#pragma unroll 4
    for (int k = 0; k < 32; k++) {
        float4 wv = __ldg(Wr + k);
        float4 y0 = __ldg(Y + k);
        float4 y1 = __ldg(Y + 32 + k);
        float4 y2 = __ldg(Y + 64 + k);
        float4 y3 = __ldg(Y + 96 + k);
        a0 += wv.x * y0.x + wv.y * y0.y + wv.z * y0.z + wv.w * y0.w;
        a1 += wv.x * y1.x + wv.y * y1.y + wv.z * y1.z + wv.w * y1.w;
        a2 += wv.x * y2.x + wv.y * y2.y + wv.z * y2.z + wv.w * y2.w;
        a3 += wv.x * y3.x + wv.y * y3.y + wv.z * y3.z + wv.w * y3.w;
    }
    const float bias = __ldg(b_ih + h);
    size_t base = ((size_t)b * Tn + t0) * Hn + h;
    g_xproj[base]          = a0 + bias;
    g_xproj[base + Hn]     = a1 + bias;
    g_xproj[base + 2 * Hn] = a2 + bias;
    g_xproj[base + 3 * Hn] = a3 + bias;
}

// ---------------- kernel 2: RNN scan + prec zero-fill ----------------
// Grid 256, clusters of 2. CTAs [0,32): scan. CTAs [32,256): zero-fill prec.
// Scan (k-split): CTA rank r holds W_hh[:, r*128:+128]. Thread handles TWO rows
// over a 64-wide k-quarter; merge via one shfl_xor; final row = lidx.
// NEW: peer warps fold (x + bias) into the shipped partial, so the own-warp
// tail after mbar_wait is just part + ps_in -> tanh.
__global__ void __cluster_dims__(2, 1, 1) __launch_bounds__(256, 1)
k_scan(const float* __restrict__ W_hh, const float* __restrict__ b_hh,
       float* __restrict__ prec) {
    // ---- zero-fill CTAs ----
    if (blockIdx.x >= SCAN_CTAS) {
        const long long total = (long long)Bn * Dn * Tn * Tn / 4;   // float4 count
        const int nz = GRID_SCAN - SCAN_CTAS;
        long long i = (long long)(blockIdx.x - SCAN_CTAS) * blockDim.x + threadIdx.x;
        const long long stride = (long long)nz * blockDim.x;
        const float4 z = make_float4(0.f, 0.f, 0.f, 0.f);
        for (; i < total; i += stride)
            __stcs(reinterpret_cast<float4*>(prec) + i, z);
        return;
    }

    __shared__ __align__(16) float hbuf[2][128];   // local h half, double buffered
    __shared__ __align__(16) float ps_in[2][128];  // incoming peer partials (incl. x+bias)
    __shared__ __align__(8) unsigned long long mbar[2];

    const int tid  = threadIdx.x;
    const int lidx = tid & 127;
    const int q    = lidx & 1;                     // k-quarter within local half
    const unsigned rank = cluster_rank();
    const unsigned peer = rank ^ 1;
    const int batch = blockIdx.x >> 1;
    const bool own  = (tid < 128);                 // warps 0-3 = own rows
    const int roleBase = (int)(((unsigned)rank << 7) ^ (tid & 128));
    const int jg = roleBase | lidx;                // this thread's OUTPUT row

    // register-resident weights: TWO rows x 64 cols (k-quarter q of local half)
    unsigned long long wA[32], wB[32];
    {
        const int kb = (int)(rank << 7) + (q << 6);
        const float2* wrA = reinterpret_cast<const float2*>(
            W_hh + (size_t)(roleBase | (lidx & ~1)) * Hn + kb);
        const float2* wrB = reinterpret_cast<const float2*>(
            W_hh + (size_t)(roleBase | lidx | 1) * Hn + kb);
#pragma unroll
        for (int i = 0; i < 32; i++) {
            float2 a = __ldg(wrA + i);
            float2 b = __ldg(wrB + i);
            wA[i] = pack2(a.x, a.y);
            wB[i] = pack2(b.x, b.y);
        }
    }
    // peer warps carry x+bias for the rows they ship
    const float bias = (!own) ? __ldg(b_hh + jg) : 0.f;
    const float* xcol = g_xproj + (size_t)batch * Tn * Hn + jg;

    if (tid == 0) { mbar_init(smem_u32(&mbar[0]), 1); mbar_init(smem_u32(&mbar[1]), 1); }
    if (own) hbuf[0][lidx] = 0.f;   // h(-1) = 0
    __syncthreads();
    asm volatile("barrier.cluster.arrive.aligned;" ::: "memory");
    asm volatile("barrier.cluster.wait.aligned;" ::: "memory");

    // remote addresses (peer CTA)
    const uint32_t r_ps[2]   = { mapa_u32(smem_u32(&ps_in[0][lidx]), peer),
                                 mapa_u32(smem_u32(&ps_in[1][lidx]), peer) };
    const uint32_t r_mbar[2] = { mapa_u32(smem_u32(&mbar[0]), peer),
                                 mapa_u32(smem_u32(&mbar[1]), peer) };
    const uint32_t l_mbar[2] = { smem_u32(&mbar[0]), smem_u32(&mbar[1]) };

    int ph[2] = {0, 0};
    float xv = (!own) ? (__ldg(xcol) + bias) : 0.f;   // x(0)+bias for shipped row

    for (int t = 0; t < Tn; ++t) {
        const int buf = t & 1;
        const int nb  = buf ^ 1;

        // post tx expectation for this step's incoming 512 bytes
        if (tid == 0) mbar_arrive_expect_tx(l_mbar[buf], 512);

        // 64-wide dot for TWO rows over k-quarter q (16 LDS.128)
        const ulonglong2* hp = reinterpret_cast<const ulonglong2*>(&hbuf[buf][q << 6]);
        unsigned long long aA0 = 0ull, aA1 = 0ull, aB0 = 0ull, aB1 = 0ull;
#pragma unroll
        for (int i = 0; i < 16; i++) {
            ulonglong2 hv = hp[i];
            ffma2(aA0, wA[2 * i],     hv.x);
            ffma2(aA1, wA[2 * i + 1], hv.y);
            ffma2(aB0, wB[2 * i],     hv.x);
            ffma2(aB1, wB[2 * i + 1], hv.y);
        }
        float u0, u1, v0, v1;
        unpack2(aA0, u0, u1); unpack2(aA1, v0, v1);
        const float sA = (u0 + v0) + (u1 + v1);
        unpack2(aB0, u0, u1); unpack2(aB1, v0, v1);
        const float sB = (u0 + v0) + (u1 + v1);

        // merge k-quarters: even lane keeps row lidx(=2p), odd keeps row 2p+1
        const float send = q ? sA : sB;
        const float recv = __shfl_xor_sync(0xffffffffu, send, 1);
        const float part = q ? (recv + sB) : (sA + recv);

        if (!own) {
            // ship partial + x + bias; drains in background
            st_async_f32(r_ps[buf], part + xv, r_mbar[buf]);
            // prefetch next x+bias off the critical path
            if ((t + 1) < Tn) xv = __ldg(xcol + (size_t)(t + 1) * Hn) + bias;
        } else {
            mbar_wait(l_mbar[buf], ph[buf]);
            ph[buf] ^= 1;
            float hn = tanh_approx(part + ps_in[buf][lidx]);
            hbuf[nb][lidx] = hn;                               // STS first (releases peers sooner)
            g_enc[((size_t)batch * Tn + t) * Hn + jg] = hn;    // then global
        }
        __syncthreads();
    }

    // keep smem/barriers alive until peer's in-flight st.asyncs complete
    asm volatile("barrier.cluster.arrive.aligned;" ::: "memory");
    asm volatile("barrier.cluster.wait.aligned;" ::: "memory");
}

// ---------------- kernel 3: mean + bd heads (enc staged in smem) ----------------
__global__ void __launch_bounds__(192) k_meanbd(
        const float* __restrict__ W_mean, const float* __restrict__ b_mean,
        const float* __restrict__ W_bd,   const float* __restrict__ b_bd,
        float* __restrict__ out_mean) {
    __shared__ __align__(16) float erow[8][Hn];    // 8 KB: 8 enc rows

    const int tid = threadIdx.x;              // 0..191
    const int bt0 = blockIdx.x * 8;

    // cooperative load of 8 enc rows (512 float4)
    {
        const float4* src = reinterpret_cast<const float4*>(g_enc + (size_t)bt0 * Hn);
        float4* dst = reinterpret_cast<float4*>(&erow[0][0]);
        for (int i = tid; i < 512; i += 192)
            dst[i] = __ldg(src + i);
    }
    __syncthreads();

    const int o = tid % 24;
    const int r = tid / 24;
    const int bt = bt0 + r;

    const float4* e4 = reinterpret_cast<const float4*>(&erow[r][0]);
    const float4* w4;
    float bias;
    if (o < Dn) { w4 = reinterpret_cast<const float4*>(W_mean + o * Hn);        bias = __ldg(b_mean + o); }
    else        { w4 = reinterpret_cast<const float4*>(W_bd + (o - Dn) * Hn);   bias = __ldg(b_bd + (o - Dn)); }

    float acc = 0.f;
#pragma unroll 8
    for (int k = 0; k < 64; k++) {
        float4 ev = e4[k];
        float4 wv = __ldg(w4 + k);
        acc += ev.x * wv.x + ev.y * wv.y + ev.z * wv.z + ev.w * wv.w;
    }
    acc += bias;
    if (o < Dn) out_mean[(size_t)bt * Dn + o] = acc;
    else        g_bd[(size_t)bt * (2 * Dn) + (o - Dn)] = acc;
}

// ---------------- kernel 4: tridiagonal writes only (zeros done in k_scan) ----------------
__global__ void __launch_bounds__(256) k_prec_diag(float* __restrict__ prec) {
    const int idx = blockIdx.x * 256 + threadIdx.x;   // 0 .. 65535 = (b*8+d)*512 + i
    const int i   = idx & 511;
    const int bd_ = idx >> 9;
    const int d   = bd_ & 7;
    const int b   = bd_ >> 3;

    const size_t row = ((size_t)b * Tn + i) * 16;
    float diag_i = g_bd[row + d];
    float off_i  = g_bd[row + 8 + d];
    float off_p  = 0.f;
    if (i > 0) off_p = g_bd[row - 16 + 8 + d];

    float mainv  = diag_i * diag_i + off_p * off_p + EPSf;
    float supd_r = diag_i * off_i;   // supd[i] (columns i/i+1)

    float* base = prec + ((size_t)bd_ * Tn + i) * Tn + i;   // [b,d,i,i]
    base[0] = mainv;
    if (i < Tn - 1) {
        base[1]  = supd_r;    // [i, i+1]
        base[Tn] = supd_r;    // [i+1, i]
    }
}

// ---------------- launch ----------------
extern "C" void kernel_launch(void* const* d_in, const int* in_sizes, int n_in,
                              void* d_out, int out_size) {
    const float* y      = (const float*)d_in[0];
    const float* W_ih   = (const float*)d_in[1];
    const float* W_hh   = (const float*)d_in[2];
    const float* b_ih   = (const float*)d_in[3];
    const float* b_hh   = (const float*)d_in[4];
    const float* W_mean = (const float*)d_in[5];
    const float* b_mean = (const float*)d_in[6];
    const float* W_bd   = (const float*)d_in[7];
    const float* b_bd   = (const float*)d_in[8];
    float* out = (float*)d_out;
    float* prec = out + Bn * Tn * Dn;

    k_xproj<<<dim3(Tn / 4, Bn), 256>>>(y, W_ih, b_ih);
    k_scan<<<GRID_SCAN, 256>>>(W_hh, b_hh, prec);          // scan + prec zero-fill
    k_meanbd<<<(Bn * Tn) / 8, 192>>>(W_mean, b_mean, W_bd, b_bd, out);
    k_prec_diag<<<(Bn * Dn * Tn) / 256, 256>>>(prec);
}

// round 11
// speedup vs baseline: 1.2652x; 1.2652x over previous
#include <cuda_runtime.h>
#include <cstdint>

#define Bn   16
#define Tn   512
#define INn  128
#define Hn   256
#define Dn   8
#define EPSf 1e-5f

#define CL        4            // CTAs per cluster (4-way k/row split)
#define SCAN_CTAS 64           // 16 batches x 4 CTAs
#define GRID_SCAN 256          // 64 scan CTAs + 192 zero-fill CTAs

// ---------------- scratch (static device arrays; no allocation) ----------------
__device__ float g_xproj[Bn * Tn * Hn];   // 8 MB
__device__ float g_enc  [Bn * Tn * Hn];   // 8 MB
__device__ float g_bd   [Bn * Tn * 2 * Dn]; // 512 KB

// ---------------- helpers ----------------
__device__ __forceinline__ uint32_t smem_u32(const void* p) {
    uint32_t a;
    asm("{ .reg .u64 t; cvta.to.shared.u64 t, %1; cvt.u32.u64 %0, t; }"
        : "=r"(a) : "l"(p));
    return a;
}

__device__ __forceinline__ uint32_t cluster_rank() {
    uint32_t r;
    asm("mov.u32 %0, %%cluster_ctarank;" : "=r"(r));
    return r;
}

__device__ __forceinline__ uint32_t mapa_u32(uint32_t local_addr, uint32_t rank) {
    uint32_t r;
    asm("mapa.shared::cluster.u32 %0, %1, %2;" : "=r"(r) : "r"(local_addr), "r"(rank));
    return r;
}

__device__ __forceinline__ unsigned long long pack2(float x, float y) {
    unsigned long long r;
    asm("mov.b64 %0, {%1, %2};" : "=l"(r) : "f"(x), "f"(y));
    return r;
}
__device__ __forceinline__ void unpack2(unsigned long long v, float& x, float& y) {
    asm("mov.b64 {%0, %1}, %2;" : "=f"(x), "=f"(y) : "l"(v));
}
// packed fp32x2 FMA (Blackwell FFMA2): 2 fp32 MACs per instruction
__device__ __forceinline__ void ffma2(unsigned long long& d,
                                      unsigned long long a,
                                      unsigned long long b) {
    asm("fma.rn.f32x2 %0, %1, %2, %3;" : "=l"(d) : "l"(a), "l"(b), "l"(d));
}

__device__ __forceinline__ float tanh_approx(float x) {
    float r;
    asm("tanh.approx.f32 %0, %1;" : "=f"(r) : "f"(x));
    return r;
}

__device__ __forceinline__ void mbar_init(uint32_t addr, uint32_t count) {
    asm volatile("mbarrier.init.shared.b64 [%0], %1;" :: "r"(addr), "r"(count) : "memory");
}

__device__ __forceinline__ void mbar_arrive_expect_tx(uint32_t addr, uint32_t bytes) {
    asm volatile("mbarrier.arrive.expect_tx.shared.b64 _, [%0], %1;"
                 :: "r"(addr), "r"(bytes) : "memory");
}

__device__ __forceinline__ void mbar_wait(uint32_t addr, int phase) {
    asm volatile(
        "{\n\t"
        ".reg .pred P1;\n\t"
        "LAB_%=:\n\t"
        "mbarrier.try_wait.parity.acquire.cta.shared::cta.b64 P1, [%0], %1, 0x989680;\n\t"
        "@P1 bra DONE_%=;\n\t"
        "bra LAB_%=;\n\t"
        "DONE_%=:\n\t"
        "}"
        :: "r"(addr), "r"(phase) : "memory");
}

// async remote smem store (b32) with tx-completion on the remote mbarrier
__device__ __forceinline__ void st_async_f32(uint32_t raddr, float v, uint32_t rmbar) {
    asm volatile(
        "st.async.shared::cluster.mbarrier::complete_tx::bytes.b32 [%0], %1, [%2];"
        :: "r"(raddr), "r"(__float_as_uint(v)), "r"(rmbar) : "memory");
}

// ---------------- kernel 1: x_proj = y @ W_ih^T + b_ih ----------------
__global__ void k_xproj(const float* __restrict__ y,
                        const float* __restrict__ W_ih,
                        const float* __restrict__ b_ih) {
    const int h  = threadIdx.x;       // 0..255
    const int b  = blockIdx.y;
    const int t0 = blockIdx.x * 4;

    const float4* Wr = reinterpret_cast<const float4*>(W_ih + h * INn);
    const float4* Y  = reinterpret_cast<const float4*>(y + ((size_t)b * Tn + t0) * INn);

    float a0 = 0.f, a1 = 0.f, a2 = 0.f, a3 = 0.f;
#pragma unroll 4
    for (int k = 0; k < 32; k++) {
        float4 wv = __ldg(Wr + k);
        float4 y0 = __ldg(Y + k);
        float4 y1 = __ldg(Y + 32 + k);
        float4 y2 = __ldg(Y + 64 + k);
        float4 y3 = __ldg(Y + 96 + k);
        a0 += wv.x * y0.x + wv.y * y0.y + wv.z * y0.z + wv.w * y0.w;
        a1 += wv.x * y1.x + wv.y * y1.y + wv.z * y1.z + wv.w * y1.w;
        a2 += wv.x * y2.x + wv.y * y2.y + wv.z * y2.z + wv.w * y2.w;
        a3 += wv.x * y3.x + wv.y * y3.y + wv.z * y3.z + wv.w * y3.w;
    }
    const float bias = __ldg(b_ih + h);
    size_t base = ((size_t)b * Tn + t0) * Hn + h;
    g_xproj[base]          = a0 + bias;
    g_xproj[base + Hn]     = a1 + bias;
    g_xproj[base + 2 * Hn] = a2 + bias;
    g_xproj[base + 3 * Hn] = a3 + bias;
}

// ---------------- kernel 2: RNN scan (4-way cluster split) + prec zero-fill ----------------
// Grid 256, clusters of 4. CTAs [0,64): scan (16 clusters, one per batch).
// CTAs [64,256): zero-fill prec on otherwise-idle SMs.
// Scan: CTA rank r holds W_hh[:, r*64:+64) (thread tid = output row, 32 f32x2
// regs) and OWNS output rows [r*64,+64) — matching row/k split means each CTA
// only ever needs the h-slice it finalizes; only partials cross CTAs.
// Per step: 64-wide dot (¼ the FMA of 2-way), non-own threads ship partial to
// the row's owner via st.async; owner's 64 finalizer threads wait on mbar
// (768 B = 3 sources x 64 rows), sum 4 slots (own slot pre-zeroed), tanh.
__global__ void __cluster_dims__(CL, 1, 1) __launch_bounds__(256, 1)
k_scan(const float* __restrict__ W_hh, const float* __restrict__ b_hh,
       float* __restrict__ prec) {
    // ---- zero-fill CTAs ----
    if (blockIdx.x >= SCAN_CTAS) {
        const long long total = (long long)Bn * Dn * Tn * Tn / 4;   // float4 count
        const int nz = GRID_SCAN - SCAN_CTAS;
        long long i = (long long)(blockIdx.x - SCAN_CTAS) * blockDim.x + threadIdx.x;
        const long long stride = (long long)nz * blockDim.x;
        const float4 z = make_float4(0.f, 0.f, 0.f, 0.f);
        for (; i < total; i += stride)
            __stcs(reinterpret_cast<float4*>(prec) + i, z);
        return;
    }

    __shared__ __align__(16) float hbuf[2][64];      // this CTA's OWNED h slice
    __shared__ __align__(16) float ps_in[2][CL][64]; // incoming partials by source rank
    __shared__ __align__(8) unsigned long long mbar[2];

    const int tid = threadIdx.x;                 // = global output row
    const unsigned rank = cluster_rank();        // 0..3
    const int batch = blockIdx.x >> 2;
    const unsigned owner = (unsigned)tid >> 6;   // owner CTA of this row
    const bool own = (owner == rank);
    const int lrow = tid & 63;

    // register-resident weights: W_hh[tid, rank*64 .. +64)  (32 f32x2)
    unsigned long long w[32];
    {
        const float2* wr = reinterpret_cast<const float2*>(W_hh + (size_t)tid * Hn + (rank << 6));
#pragma unroll
        for (int i = 0; i < 32; i++) {
            float2 v = __ldg(wr + i);
            w[i] = pack2(v.x, v.y);
        }
    }
    const float bias = own ? __ldg(b_hh + tid) : 0.f;
    const float* xcol = g_xproj + (size_t)batch * Tn * Hn + tid;

    if (tid == 0) { mbar_init(smem_u32(&mbar[0]), 1); mbar_init(smem_u32(&mbar[1]), 1); }
    if (tid < 64) { hbuf[0][tid] = 0.f; }                       // h(-1) = 0
    for (int i = tid; i < 2 * CL * 64; i += 256)                // zero ps_in (own slot stays 0)
        reinterpret_cast<float*>(ps_in)[i] = 0.f;
    __syncthreads();
    asm volatile("barrier.cluster.arrive.aligned;" ::: "memory");
    asm volatile("barrier.cluster.wait.aligned;" ::: "memory");

    // remote targets for shippers: slot [buf][my_rank][lrow] in owner CTA
    uint32_t r_ps[2] = {0, 0}, r_mbar[2] = {0, 0};
    if (!own) {
        r_ps[0]   = mapa_u32(smem_u32(&ps_in[0][rank][lrow]), owner);
        r_ps[1]   = mapa_u32(smem_u32(&ps_in[1][rank][lrow]), owner);
        r_mbar[0] = mapa_u32(smem_u32(&mbar[0]), owner);
        r_mbar[1] = mapa_u32(smem_u32(&mbar[1]), owner);
    }
    const uint32_t l_mbar[2] = { smem_u32(&mbar[0]), smem_u32(&mbar[1]) };

    int ph[2] = {0, 0};
    float xv = own ? __ldg(xcol) : 0.f;   // x for t=0

    for (int t = 0; t < Tn; ++t) {
        const int buf = t & 1;
        const int nb  = buf ^ 1;

        // prefetch next x (finalizer threads), latency hidden behind FMA
        float xnext = 0.f;
        if (own && (t + 1) < Tn) xnext = __ldg(xcol + (size_t)(t + 1) * Hn);

        // expect 3 sources x 64 rows x 4 B
        if (tid == 0) mbar_arrive_expect_tx(l_mbar[buf], 768);

        // 64-wide dot over owned h slice (8 LDS.128, 32 FFMA2)
        const ulonglong2* hp = reinterpret_cast<const ulonglong2*>(hbuf[buf]);
        unsigned long long acc0 = 0ull, acc1 = 0ull;
#pragma unroll
        for (int i = 0; i < 16; i++) {
            ulonglong2 hv = hp[i];
            ffma2(acc0, w[2 * i],     hv.x);
            ffma2(acc1, w[2 * i + 1], hv.y);
        }
        float a0, a1, c0, c1;
        unpack2(acc0, a0, a1);
        unpack2(acc1, c0, c1);
        const float part = (a0 + c0) + (a1 + c1);

        if (!own) {
            // ship partial to the row's owner; drains in background
            st_async_f32(r_ps[buf], part, r_mbar[buf]);
        } else {
            mbar_wait(l_mbar[buf], ph[buf]);
            ph[buf] ^= 1;
            // own slot is permanently 0 -> unconditional 4-way sum
            float s = part + xv + bias
                    + ps_in[buf][0][lrow] + ps_in[buf][1][lrow]
                    + ps_in[buf][2][lrow] + ps_in[buf][3][lrow];
            float hn = tanh_approx(s);
            xv = xnext;
            hbuf[nb][lrow] = hn;                               // STS first
            g_enc[((size_t)batch * Tn + t) * Hn + tid] = hn;   // then global
        }
        __syncthreads();
    }

    // keep smem/barriers alive until peers' in-flight st.asyncs complete
    asm volatile("barrier.cluster.arrive.aligned;" ::: "memory");
    asm volatile("barrier.cluster.wait.aligned;" ::: "memory");
}

// ---------------- kernel 3: mean + bd heads (R9 version) ----------------
__global__ void k_meanbd(const float* __restrict__ W_mean, const float* __restrict__ b_mean,
                         const float* __restrict__ W_bd,   const float* __restrict__ b_bd,
                         float* __restrict__ out_mean) {
    const int local = threadIdx.x;            // 0..191
    const int o  = local % 24;
    const int r  = local / 24;
    const int bt = blockIdx.x * 8 + r;        // 0..8191

    const float4* e4 = reinterpret_cast<const float4*>(g_enc + (size_t)bt * Hn);
    const float4* w4;
    float bias;
    if (o < Dn) { w4 = reinterpret_cast<const float4*>(W_mean + o * Hn);        bias = __ldg(b_mean + o); }
    else        { w4 = reinterpret_cast<const float4*>(W_bd + (o - Dn) * Hn);   bias = __ldg(b_bd + (o - Dn)); }

    float acc = 0.f;
#pragma unroll 8
    for (int k = 0; k < 64; k++) {
        float4 ev = __ldg(e4 + k);
        float4 wv = __ldg(w4 + k);
        acc += ev.x * wv.x + ev.y * wv.y + ev.z * wv.z + ev.w * wv.w;
    }
    acc += bias;
    if (o < Dn) out_mean[(size_t)bt * Dn + o] = acc;
    else        g_bd[(size_t)bt * (2 * Dn) + (o - Dn)] = acc;
}

// ---------------- kernel 4: tridiagonal writes only (zeros done in k_scan) ----------------
__global__ void __launch_bounds__(256) k_prec_diag(float* __restrict__ prec) {
    const int idx = blockIdx.x * 256 + threadIdx.x;   // 0 .. 65535 = (b*8+d)*512 + i
    const int i   = idx & 511;
    const int bd_ = idx >> 9;
    const int d   = bd_ & 7;
    const int b   = bd_ >> 3;

    const size_t row = ((size_t)b * Tn + i) * 16;
    float diag_i = g_bd[row + d];
    float off_i  = g_bd[row + 8 + d];
    float off_p  = 0.f;
    if (i > 0) off_p = g_bd[row - 16 + 8 + d];

    float mainv  = diag_i * diag_i + off_p * off_p + EPSf;
    float supd_r = diag_i * off_i;   // supd[i] (columns i/i+1)

    float* base = prec + ((size_t)bd_ * Tn + i) * Tn + i;   // [b,d,i,i]
    base[0] = mainv;
    if (i < Tn - 1) {
        base[1]  = supd_r;    // [i, i+1]
        base[Tn] = supd_r;    // [i+1, i]
    }
}

// ---------------- launch ----------------
extern "C" void kernel_launch(void* const* d_in, const int* in_sizes, int n_in,
                              void* d_out, int out_size) {
    const float* y      = (const float*)d_in[0];
    const float* W_ih   = (const float*)d_in[1];
    const float* W_hh   = (const float*)d_in[2];
    const float* b_ih   = (const float*)d_in[3];
    const float* b_hh   = (const float*)d_in[4];
    const float* W_mean = (const float*)d_in[5];
    const float* b_mean = (const float*)d_in[6];
    const float* W_bd   = (const float*)d_in[7];
    const float* b_bd   = (const float*)d_in[8];
    float* out = (float*)d_out;
    float* prec = out + Bn * Tn * Dn;

    k_xproj<<<dim3(Tn / 4, Bn), 256>>>(y, W_ih, b_ih);
    k_scan<<<GRID_SCAN, 256>>>(W_hh, b_hh, prec);          // scan + prec zero-fill
    k_meanbd<<<(Bn * Tn) / 8, 192>>>(W_mean, b_mean, W_bd, b_bd, out);
    k_prec_diag<<<(Bn * Dn * Tn) / 256, 256>>>(prec);
}